// round 3
// baseline (speedup 1.0000x reference)
#include <cuda_runtime.h>
#include <cuda_fp16.h>
#include <math.h>

#define Nn 50000
#define Mm 12
#define NEe (Nn*Mm)
#define OFd 92
#define Ff 64
#define Ee 41
#define Zz 169
#define Hh 128
#define NOUT 128
#define EOUT 82
#define PSTR 512          // P row stride in halves: [0,256) self(+bias), [256,512) nbr
#define PHALF 256
#define YS_CONV 224       // conv Y stride in halves (210 real)
#define YS_FIN 256
#define NTILES (NEe/32)   // 18750
#define NBLK_EG 592

// ---------------- scratch ----------------
__device__ __align__(16) float  g_node[Nn*Ff];
__device__ __align__(16) float  g_edge[(size_t)NEe*Ee];
__device__ __align__(16) __half g_P[(size_t)Nn*PSTR];        // 51.2 MB (L2-resident)
__device__ __align__(16) __half g_Y[(size_t)NEe*256];        // 307 MB max
__device__ __align__(16) float  g_G[(size_t)NEe*Ee];
__device__ __align__(16) float  g_aggr[Nn*Ff];
__device__ __align__(16) float  g_dist[NEe];
__device__ double g_sumd[256], g_sqd[256];
__device__ float  g_mean[256], g_istd[256];
__device__ double g_sum2d[112], g_sq2d[112];
__device__ float  g_mean2[112], g_istd2[112];

typedef unsigned long long u64t;

__device__ __forceinline__ float lrelu_f(float v){ return v > 0.f ? v : 0.01f*v; }
__device__ __forceinline__ float sigm_f(float x){ return 1.f/(1.f+expf(-x)); }
__device__ __forceinline__ float splus_f(float x){ return fmaxf(x,0.f) + log1pf(expf(-fabsf(x))); }

// ---- packed f32x2 helpers (sm_103a) ----
__device__ __forceinline__ u64t dupf2(float v){
    u64t p; asm("mov.b64 %0, {%1, %1};" : "=l"(p) : "f"(v)); return p;
}
__device__ __forceinline__ u64t packf2(float x, float y){
    u64t p; asm("mov.b64 %0, {%1, %2};" : "=l"(p) : "f"(x), "f"(y)); return p;
}
__device__ __forceinline__ void ffma2(u64t &d, u64t a, u64t b){
    asm("fma.rn.f32x2 %0, %1, %2, %3;" : "=l"(d) : "l"(a), "l"(b), "l"(d));
}
__device__ __forceinline__ u64t addf2(u64t a, u64t b){
    u64t d; asm("add.rn.f32x2 %0, %1, %2;" : "=l"(d) : "l"(a), "l"(b)); return d;
}
__device__ __forceinline__ float2 unpackf2(u64t p){
    float2 r; asm("mov.b64 {%0, %1}, %2;" : "=f"(r.x), "=f"(r.y) : "l"(p)); return r;
}

// ---------------- node embedding ----------------
__global__ void k_emb(const float* __restrict__ nf, const float* __restrict__ W,
                      const float* __restrict__ b)
{
    __shared__ float srow[4][OFd];
    int n0 = blockIdx.x*4;
    for (int idx = threadIdx.x; idx < 4*OFd; idx += 256){
        int nl = idx/OFd, k = idx%OFd;
        srow[nl][k] = nf[(size_t)(n0+nl)*OFd + k];
    }
    __syncthreads();
    int c  = threadIdx.x & 63;
    int nl = threadIdx.x >> 6;
    float acc = b[c];
    #pragma unroll
    for (int k = 0; k < OFd; k++) acc += srow[nl][k]*W[k*Ff + c];
    g_node[(size_t)(n0+nl)*Ff + c] = acc;
}

// ---------------- distances ----------------
__global__ void k_dist(const float* __restrict__ off, const float* __restrict__ pos,
                       const float* __restrict__ cells, const int* __restrict__ eidx)
{
    int e = blockIdx.x*256 + threadIdx.x;
    if (e >= NEe) return;
    int n = e / Mm;
    int j = eidx[e];
    float o0 = off[(size_t)e*3+0], o1 = off[(size_t)e*3+1], o2 = off[(size_t)e*3+2];
    const float* C = cells + (size_t)n*9;
    float d0 = pos[(size_t)j*3+0] + o0*C[0] + o1*C[3] + o2*C[6] - pos[(size_t)n*3+0];
    float d1 = pos[(size_t)j*3+1] + o0*C[1] + o1*C[4] + o2*C[7] - pos[(size_t)n*3+1];
    float d2 = pos[(size_t)j*3+2] + o0*C[2] + o1*C[5] + o2*C[8] - pos[(size_t)n*3+2];
    g_dist[e] = sqrtf(d0*d0 + d1*d1 + d2*d2 + 1e-12f);
}

__global__ void k_zero()
{
    int t = threadIdx.x;
    if (t < 256){ g_sumd[t] = 0.0; g_sqd[t] = 0.0; }
    if (t < 112){ g_sum2d[t] = 0.0; g_sq2d[t] = 0.0; }
}

// ---------------- P = node @ W  (fp16 out; bias folded into self half) ----------------
// block (32,8): tx = col quad (128 cols/block), ty covers 4 nodes each (32 nodes/block)
__global__ __launch_bounds__(256)
void k_pmat(const float* __restrict__ W1, int ld1, int nc1,
            const float* __restrict__ W2, int ld2, int ncols,
            const float* __restrict__ b1, const float* __restrict__ b2)
{
    __shared__ u64t  snode2[32][Ff];    // duplicated f32 pairs, 16 KB
    __shared__ float Wsh[Ff][128];      // 32 KB
    int tx = threadIdx.x, ty = threadIdx.y;
    int tid = ty*32 + tx;
    int n0 = blockIdx.x*32;
    int cb = blockIdx.y*128;

    for (int idx = tid; idx < 32*Ff; idx += 256){
        int n = idx >> 6, k = idx & 63;
        int gn = n0 + n;
        float v = (gn < Nn) ? g_node[(size_t)gn*Ff + k] : 0.f;
        snode2[n][k] = dupf2(v);
    }
    for (int idx = tid; idx < Ff*128; idx += 256){
        int k = idx >> 7, c = idx & 127;
        int gc = cb + c;
        int half = gc >> 8;
        int cc = gc & 255;
        int r = half*Ff + k;
        float v = 0.f;
        if (cc < nc1)        v = W1[(size_t)r*ld1 + cc];
        else if (cc < ncols) v = W2[(size_t)r*ld2 + (cc - nc1)];
        Wsh[k][c] = v;
    }
    __syncthreads();

    u64t acc[4][2];
    #pragma unroll
    for (int nl = 0; nl < 4; nl++){ acc[nl][0] = 0ull; acc[nl][1] = 0ull; }

    #pragma unroll 4
    for (int k = 0; k < Ff; k++){
        ulonglong2 w = *(const ulonglong2*)&Wsh[k][tx*4];
        #pragma unroll
        for (int nl = 0; nl < 4; nl++){
            u64t a = snode2[ty*4 + nl][k];
            ffma2(acc[nl][0], a, w.x);
            ffma2(acc[nl][1], a, w.y);
        }
    }

    // bias (self half only)
    float bv[4];
    #pragma unroll
    for (int q = 0; q < 4; q++){
        int gc = cb + tx*4 + q;
        int half = gc >> 8;
        int cc = gc & 255;
        float b = 0.f;
        if (half == 0){
            if (cc < nc1)        b = b1[cc];
            else if (cc < ncols) b = b2[cc - nc1];
        }
        bv[q] = b;
    }

    #pragma unroll
    for (int nl = 0; nl < 4; nl++){
        int gn = n0 + ty*4 + nl;
        if (gn < Nn){
            float2 f0 = unpackf2(acc[nl][0]);
            float2 f1 = unpackf2(acc[nl][1]);
            __half2 h0 = __floats2half2_rn(f0.x + bv[0], f0.y + bv[1]);
            __half2 h1 = __floats2half2_rn(f1.x + bv[2], f1.y + bv[3]);
            uint2 o;
            o.x = *reinterpret_cast<unsigned*>(&h0);
            o.y = *reinterpret_cast<unsigned*>(&h1);
            *reinterpret_cast<uint2*>(g_P + (size_t)gn*PSTR + cb + tx*4) = o;
        }
    }
}

// ---------------- edge GEMM + fused BN column stats (fp16 Y out) ----------------
// block (CG8, 8): tx = column group of 8, ty = edge group of 4 (32 edges/tile)
template<int CG8, int YSTR, int NCOLS>
__global__ __launch_bounds__(256)
void k_egemm(const float* __restrict__ ein, const int* __restrict__ eidx,
             const float* __restrict__ W1, int ld1,
             const float* __restrict__ W2, int ld2, int nc1)
{
    constexpr int COLS = CG8*8;
    extern __shared__ float smp[];
    float*  Wsh   = smp;                          // 41*COLS floats
    u64t*   ser2  = (u64t*)(Wsh + Ee*COLS);       // 32*41 dup pairs
    int*    sidx  = (int*)(ser2 + 32*Ee);         // 32
    double* sstat = (double*)(sidx + 32);         // 2*COLS

    const float* ei = ein ? ein : g_edge;
    int tx = threadIdx.x, ty = threadIdx.y;
    int tid = ty*CG8 + tx;
    const int nthr = CG8*8;

    for (int idx = tid; idx < Ee*COLS; idx += nthr){
        int k = idx / COLS, c = idx % COLS;
        float v = 0.f;
        if (c < nc1)        v = W1[(size_t)k*ld1 + c];
        else if (c < NCOLS) v = W2[(size_t)k*ld2 + (c - nc1)];
        Wsh[idx] = v;
    }
    for (int i = tid; i < 2*COLS; i += nthr) sstat[i] = 0.0;

    u64t s2[4] = {0,0,0,0}, q2[4] = {0,0,0,0};
    int ebase = ty*4;

    for (int t = blockIdx.x; t < NTILES; t += gridDim.x){
        int e0 = t*32;
        __syncthreads();
        for (int idx = tid; idx < 32*Ee; idx += nthr)
            ser2[idx] = dupf2(ei[(size_t)e0*Ee + idx]);
        if (tid < 32) sidx[tid] = eidx[e0 + tid];
        __syncthreads();

        u64t acc[4][4];
        #pragma unroll
        for (int el = 0; el < 4; el++){
            int e = e0 + ebase + el;
            int i = e / Mm;
            int j = sidx[ebase + el];
            uint4 pv = *(const uint4*)(g_P + (size_t)i*PSTR + tx*8);
            uint4 nv = *(const uint4*)(g_P + (size_t)j*PSTR + PHALF + tx*8);
            const __half2* ph = (const __half2*)&pv;
            const __half2* nh = (const __half2*)&nv;
            #pragma unroll
            for (int p = 0; p < 4; p++){
                float2 a = __half22float2(ph[p]);
                float2 b = __half22float2(nh[p]);
                acc[el][p] = packf2(a.x + b.x, a.y + b.y);
            }
        }

        #pragma unroll 1
        for (int k = 0; k < Ee; k++){
            const ulonglong2* w2 = (const ulonglong2*)(Wsh + k*COLS + tx*8);
            ulonglong2 wA = w2[0], wB = w2[1];
            #pragma unroll
            for (int el = 0; el < 4; el++){
                u64t a = ser2[(ebase + el)*Ee + k];
                ffma2(acc[el][0], a, wA.x);
                ffma2(acc[el][1], a, wA.y);
                ffma2(acc[el][2], a, wB.x);
                ffma2(acc[el][3], a, wB.y);
            }
        }

        #pragma unroll
        for (int el = 0; el < 4; el++){
            __half2 h[4];
            #pragma unroll
            for (int p = 0; p < 4; p++){
                s2[p] = addf2(s2[p], acc[el][p]);
                ffma2(q2[p], acc[el][p], acc[el][p]);
                float2 f = unpackf2(acc[el][p]);
                h[p] = __floats2half2_rn(f.x, f.y);
            }
            uint4 o;
            o.x = *reinterpret_cast<unsigned*>(&h[0]);
            o.y = *reinterpret_cast<unsigned*>(&h[1]);
            o.z = *reinterpret_cast<unsigned*>(&h[2]);
            o.w = *reinterpret_cast<unsigned*>(&h[3]);
            *reinterpret_cast<uint4*>(g_Y + (size_t)(e0 + ebase + el)*YSTR + tx*8) = o;
        }
    }

    __syncthreads();
    #pragma unroll
    for (int p = 0; p < 4; p++){
        float2 sv = unpackf2(s2[p]);
        float2 qv = unpackf2(q2[p]);
        int c = tx*8 + 2*p;
        if (c < NCOLS){
            atomicAdd(&sstat[c], (double)sv.x);
            atomicAdd(&sstat[COLS + c], (double)qv.x);
        }
        if (c+1 < NCOLS){
            atomicAdd(&sstat[c+1], (double)sv.y);
            atomicAdd(&sstat[COLS + c + 1], (double)qv.y);
        }
    }
    __syncthreads();
    for (int c = tid; c < COLS; c += nthr){
        if (c < NCOLS){
            atomicAdd(&g_sumd[c], sstat[c]);
            atomicAdd(&g_sqd[c],  sstat[COLS + c]);
        }
    }
}

__global__ void k_finalize(int ncols, double inv_count)
{
    int c = threadIdx.x;
    if (c < ncols){
        double m = g_sumd[c]*inv_count;
        double var = g_sqd[c]*inv_count - m*m;
        g_mean[c] = (float)m;
        g_istd[c] = (float)(1.0/sqrt(var + 1e-5));
    }
}

// ---------------- gate + aggregate ----------------
__global__ void k_gate()
{
    __shared__ float ssum[112], ssq[112];
    for (int i = threadIdx.x; i < 112; i += 256){ ssum[i] = 0.f; ssq[i] = 0.f; }
    __syncthreads();

    int n    = blockIdx.x*8 + (threadIdx.x >> 5);
    int lane = threadIdx.x & 31;

    {
        int c0 = lane, c1 = lane + 32;
        float mf0 = g_mean[c0],    if0 = g_istd[c0];
        float mc0 = g_mean[64+c0], ic0 = g_istd[64+c0];
        float mf1 = g_mean[c1],    if1 = g_istd[c1];
        float mc1 = g_mean[64+c1], ic1 = g_istd[64+c1];
        float a0 = 0.f, a1 = 0.f;
        #pragma unroll
        for (int m = 0; m < Mm; m++){
            const __half* y = g_Y + (size_t)(n*Mm + m)*YS_CONV;
            float vf = (__half2float(y[c0])    - mf0)*if0;
            float vc = (__half2float(y[64+c0]) - mc0)*ic0;
            a0 += sigm_f(vf)*lrelu_f(vc);
            vf = (__half2float(y[c1])    - mf1)*if1;
            vc = (__half2float(y[64+c1]) - mc1)*ic1;
            a1 += sigm_f(vf)*lrelu_f(vc);
        }
        g_aggr[(size_t)n*64 + c0] = a0;
        g_aggr[(size_t)n*64 + c1] = a1;
        atomicAdd(&ssum[c0], a0); atomicAdd(&ssq[c0], a0*a0);
        atomicAdd(&ssum[c1], a1); atomicAdd(&ssq[c1], a1*a1);
    }

    {
        int c0 = lane;
        int c1 = lane + 32;
        bool has1 = (c1 < Ee);
        float mf0 = g_mean[128+c0], if0 = g_istd[128+c0];
        float mc0 = g_mean[169+c0], ic0 = g_istd[169+c0];
        float mf1 = 0.f, if1 = 0.f, mc1 = 0.f, ic1 = 0.f;
        if (has1){
            mf1 = g_mean[128+c1]; if1 = g_istd[128+c1];
            mc1 = g_mean[169+c1]; ic1 = g_istd[169+c1];
        }
        float es0 = 0.f, eq0 = 0.f, es1 = 0.f, eq1 = 0.f;
        #pragma unroll
        for (int m = 0; m < Mm; m++){
            const __half* y = g_Y + (size_t)(n*Mm + m)*YS_CONV;
            float vf = (__half2float(y[128+c0]) - mf0)*if0;
            float vc = (__half2float(y[169+c0]) - mc0)*ic0;
            float ge = sigm_f(vf)*lrelu_f(vc);
            g_G[(size_t)(n*Mm + m)*Ee + c0] = ge;
            es0 += ge; eq0 += ge*ge;
            if (has1){
                vf = (__half2float(y[128+c1]) - mf1)*if1;
                vc = (__half2float(y[169+c1]) - mc1)*ic1;
                float ge1 = sigm_f(vf)*lrelu_f(vc);
                g_G[(size_t)(n*Mm + m)*Ee + c1] = ge1;
                es1 += ge1; eq1 += ge1*ge1;
            }
        }
        atomicAdd(&ssum[64+c0], es0); atomicAdd(&ssq[64+c0], eq0);
        if (has1){ atomicAdd(&ssum[64+c1], es1); atomicAdd(&ssq[64+c1], eq1); }
    }

    __syncthreads();
    for (int i = threadIdx.x; i < 105; i += 256){
        atomicAdd(&g_sum2d[i], (double)ssum[i]);
        atomicAdd(&g_sq2d[i],  (double)ssq[i]);
    }
}

__global__ void k_finalize2()
{
    int c = threadIdx.x;
    if (c < 105){
        double cnt = (c < 64) ? (double)Nn : (double)NEe;
        double m = g_sum2d[c]/cnt;
        double var = g_sq2d[c]/cnt - m*m;
        g_mean2[c] = (float)m;
        g_istd2[c] = (float)(1.0/sqrt(var + 1e-5));
    }
}

// ---------------- residual updates ----------------
__global__ void k_update(const float* __restrict__ edge_input)
{
    const int NA = Nn*Ff;
    int idx = blockIdx.x*256 + threadIdx.x;
    if (idx < NA){
        int c = idx & 63;
        float a = (g_aggr[idx] - g_mean2[c])*g_istd2[c];
        float v = g_node[idx] + a;
        g_node[idx] = lrelu_f(v);
    } else {
        size_t id2 = (size_t)idx - NA;
        if (id2 < (size_t)NEe*Ee){
            int c = (int)(id2 % Ee);
            float ge = (g_G[id2] - g_mean2[64+c])*g_istd2[64+c];
            const float* eiv = edge_input ? edge_input : g_edge;
            float v = eiv[id2] + ge;
            g_edge[id2] = lrelu_f(v);
        }
    }
}

// ---------------- output heads ----------------
__global__ void k_out(float* __restrict__ out)
{
    int e    = (blockIdx.x*256 + threadIdx.x) >> 5;
    int lane = threadIdx.x & 31;
    if (e >= NEe) return;
    const __half* y = g_Y + (size_t)e*YS_FIN;
    float d = g_dist[e];
    float sd = 0.f, sc = 0.f;
    #pragma unroll
    for (int jj = 0; jj < 4; jj++){
        int c = lane + 32*jj;
        float v = (__half2float(y[c]) - g_mean[c])*g_istd[c] + d;
        sd += splus_f(v);
        int c2 = 128 + c;
        float v2 = (__half2float(y[c2]) - g_mean[c2])*g_istd[c2];
        sc += splus_f(v2);
    }
    #pragma unroll
    for (int o = 16; o > 0; o >>= 1){
        sd += __shfl_down_sync(0xffffffffu, sd, o);
        sc += __shfl_down_sync(0xffffffffu, sc, o);
    }
    if (lane == 0){
        out[(size_t)e*2 + 0] = sd*(1.f/128.f);
        out[(size_t)e*2 + 1] = sc*(1.f/(128.f*(float)Nn));
    }
}

// ---------------- host orchestration ----------------
extern "C" void kernel_launch(void* const* d_in, const int* in_sizes, int n_in,
                              void* d_out, int out_size)
{
    const float* node_fea = (const float*)d_in[0];
    const float* edge_fea = (const float*)d_in[1];
    const float* nbr_off  = (const float*)d_in[2];
    const float* atom_pos = (const float*)d_in[3];
    const float* cells    = (const float*)d_in[4];
    const int*   edge_idx = (const int*)d_in[5];
    const float* W_emb = (const float*)d_in[6];
    const float* b_emb = (const float*)d_in[7];
    const float* W_pn  = (const float*)d_in[8];
    const float* b_pn  = (const float*)d_in[9];
    const float* W_pe  = (const float*)d_in[10];
    const float* b_pe  = (const float*)d_in[11];
    const float* W_d   = (const float*)d_in[12];
    const float* b_d   = (const float*)d_in[13];
    const float* W_c   = (const float*)d_in[14];
    const float* b_c   = (const float*)d_in[15];
    float* out = (float*)d_out;

    (void)in_sizes; (void)n_in; (void)out_size;

    const int SM_CONV = Ee*224*4 + 32*Ee*8 + 32*4 + 2*224*8;  // 50944
    const int SM_FIN  = Ee*256*4 + 32*Ee*8 + 32*4 + 2*256*8;  // 56704
    cudaFuncSetAttribute((const void*)k_egemm<28,YS_CONV,210>,
                         cudaFuncAttributeMaxDynamicSharedMemorySize, SM_CONV);
    cudaFuncSetAttribute((const void*)k_egemm<32,YS_FIN,256>,
                         cudaFuncAttributeMaxDynamicSharedMemorySize, SM_FIN);

    k_emb<<<Nn/4, 256>>>(node_fea, W_emb, b_emb);
    k_dist<<<(NEe+255)/256, 256>>>(nbr_off, atom_pos, cells, edge_idx);

    const int NTOT = Nn*Ff + NEe*Ee;
    for (int l = 0; l < 3; l++){
        const float* Wn = W_pn + (size_t)l*Zz*NOUT;
        const float* We = W_pe + (size_t)l*Zz*EOUT;
        const float* bn = b_pn + l*NOUT;
        const float* be = b_pe + l*EOUT;
        const float* ein = (l == 0) ? edge_fea : nullptr;

        k_zero<<<1, 256>>>();
        k_pmat<<<dim3((Nn+31)/32, 4), dim3(32,8)>>>(Wn, NOUT, NOUT, We, EOUT, 210, bn, be);
        k_egemm<28,YS_CONV,210><<<NBLK_EG, dim3(28,8), SM_CONV>>>(
            ein, edge_idx,
            Wn + 128*NOUT, NOUT,
            We + 128*EOUT, EOUT, NOUT);
        k_finalize<<<1, 256>>>(210, 1.0/(double)NEe);
        k_gate<<<Nn/8, 256>>>();
        k_finalize2<<<1, 128>>>();
        k_update<<<(NTOT+255)/256, 256>>>(ein);
    }

    // final heads
    k_zero<<<1, 256>>>();
    k_pmat<<<dim3((Nn+31)/32, 4), dim3(32,8)>>>(W_d, Hh, Hh, W_c, Hh, 256, b_d, b_c);
    k_egemm<32,YS_FIN,256><<<NBLK_EG, dim3(32,8), SM_FIN>>>(
        nullptr, edge_idx,
        W_d + 128*Hh, Hh,
        W_c + 128*Hh, Hh, Hh);
    k_finalize<<<1, 256>>>(256, 1.0/(double)NEe);
    k_out<<<(NEe*32+255)/256, 256>>>(out);
}

// round 6
// speedup vs baseline: 1.2267x; 1.2267x over previous
#include <cuda_runtime.h>
#include <cuda_fp16.h>
#include <math.h>

#define Nn 50000
#define Mm 12
#define NEe (Nn*Mm)
#define OFd 92
#define Ff 64
#define Ee 41
#define Zz 169
#define Hh 128
#define NOUT 128
#define EOUT 82
#define PSTR 512          // P row stride in halves: [0,256) self(+bias), [256,512) nbr
#define PHALF 256
#define YS_CONV 224       // conv Y stride in floats (210 real)
#define YS_FIN 256
#define NTILE64 (NEe/64)  // 9375
#define NBLK_EG 444

// ---------------- scratch ----------------
__device__ __align__(16) float  g_node[Nn*Ff];
__device__ __align__(16) float  g_edge[(size_t)NEe*Ee];
__device__ __align__(16) __half g_P[(size_t)Nn*PSTR];        // 51.2 MB (L2-resident)
__device__ __align__(16) float  g_Y[(size_t)NEe*256];        // 614 MB
__device__ __align__(16) float  g_G[(size_t)NEe*Ee];
__device__ __align__(16) float  g_aggr[Nn*Ff];
__device__ __align__(16) float  g_dist[NEe];
__device__ double g_sumd[256], g_sqd[256];
__device__ float  g_mean[256], g_istd[256];
__device__ double g_sum2d[112], g_sq2d[112];
__device__ float  g_mean2[112], g_istd2[112];

typedef unsigned long long u64t;

__device__ __forceinline__ float lrelu_f(float v){ return v > 0.f ? v : 0.01f*v; }
__device__ __forceinline__ float sigm_f(float x){ return 1.f/(1.f+expf(-x)); }
__device__ __forceinline__ float splus_f(float x){ return fmaxf(x,0.f) + log1pf(expf(-fabsf(x))); }

// ---- packed f32x2 helpers (sm_103a) ----
__device__ __forceinline__ u64t dupf2(float v){
    u64t p; asm("mov.b64 %0, {%1, %1};" : "=l"(p) : "f"(v)); return p;
}
__device__ __forceinline__ u64t packf2(float x, float y){
    u64t p; asm("mov.b64 %0, {%1, %2};" : "=l"(p) : "f"(x), "f"(y)); return p;
}
__device__ __forceinline__ void ffma2(u64t &d, u64t a, u64t b){
    asm("fma.rn.f32x2 %0, %1, %2, %3;" : "=l"(d) : "l"(a), "l"(b), "l"(d));
}
__device__ __forceinline__ u64t addf2(u64t a, u64t b){
    u64t d; asm("add.rn.f32x2 %0, %1, %2;" : "=l"(d) : "l"(a), "l"(b)); return d;
}
__device__ __forceinline__ float2 unpackf2(u64t p){
    float2 r; asm("mov.b64 {%0, %1}, %2;" : "=f"(r.x), "=f"(r.y) : "l"(p)); return r;
}
// streaming (evict-first) 16B store
__device__ __forceinline__ void stcs16(void* p, uint4 v){
    asm volatile("st.global.cs.v4.b32 [%0], {%1,%2,%3,%4};"
                 :: "l"(p), "r"(v.x), "r"(v.y), "r"(v.z), "r"(v.w) : "memory");
}

// ---------------- node embedding ----------------
__global__ void k_emb(const float* __restrict__ nf, const float* __restrict__ W,
                      const float* __restrict__ b)
{
    __shared__ float srow[4][OFd];
    int n0 = blockIdx.x*4;
    for (int idx = threadIdx.x; idx < 4*OFd; idx += 256){
        int nl = idx/OFd, k = idx%OFd;
        srow[nl][k] = nf[(size_t)(n0+nl)*OFd + k];
    }
    __syncthreads();
    int c  = threadIdx.x & 63;
    int nl = threadIdx.x >> 6;
    float acc = b[c];
    #pragma unroll
    for (int k = 0; k < OFd; k++) acc += srow[nl][k]*W[k*Ff + c];
    g_node[(size_t)(n0+nl)*Ff + c] = acc;
}

// ---------------- distances ----------------
__global__ void k_dist(const float* __restrict__ off, const float* __restrict__ pos,
                       const float* __restrict__ cells, const int* __restrict__ eidx)
{
    int e = blockIdx.x*256 + threadIdx.x;
    if (e >= NEe) return;
    int n = e / Mm;
    int j = eidx[e];
    float o0 = off[(size_t)e*3+0], o1 = off[(size_t)e*3+1], o2 = off[(size_t)e*3+2];
    const float* C = cells + (size_t)n*9;
    float d0 = pos[(size_t)j*3+0] + o0*C[0] + o1*C[3] + o2*C[6] - pos[(size_t)n*3+0];
    float d1 = pos[(size_t)j*3+1] + o0*C[1] + o1*C[4] + o2*C[7] - pos[(size_t)n*3+1];
    float d2 = pos[(size_t)j*3+2] + o0*C[2] + o1*C[5] + o2*C[8] - pos[(size_t)n*3+2];
    g_dist[e] = sqrtf(d0*d0 + d1*d1 + d2*d2 + 1e-12f);
}

__global__ void k_zero()
{
    int t = threadIdx.x;
    if (t < 256){ g_sumd[t] = 0.0; g_sqd[t] = 0.0; }
    if (t < 112){ g_sum2d[t] = 0.0; g_sq2d[t] = 0.0; }
}

// ---------------- P = node @ W  (fp16 out; bias folded into self half) ----------------
// block (32,8): tx = col quad (128 cols/block), ty covers 8 nodes (64 nodes/block)
// grid ((Nn+63)/64, 4)
__global__ __launch_bounds__(256)
void k_pmat(const float* __restrict__ W1, int ld1, int nc1,
            const float* __restrict__ W2, int ld2, int ncols,
            const float* __restrict__ b1, const float* __restrict__ b2)
{
    extern __shared__ char smraw[];
    u64t*  snode2 = (u64t*)smraw;                 // 64 nodes x 64 k dup pairs (32 KB)
    float* Wsh    = (float*)(snode2 + 64*Ff);     // [64][128] (32 KB)
    int tx = threadIdx.x, ty = threadIdx.y;
    int tid = ty*32 + tx;
    int n0 = blockIdx.x*64;
    int cb = blockIdx.y*128;

    for (int idx = tid; idx < 64*Ff; idx += 256){
        int n = idx >> 6, k = idx & 63;
        int gn = n0 + n;
        float v = (gn < Nn) ? g_node[(size_t)gn*Ff + k] : 0.f;
        snode2[idx] = dupf2(v);
    }
    for (int idx = tid; idx < Ff*128; idx += 256){
        int k = idx >> 7, c = idx & 127;
        int gc = cb + c;
        int half = gc >> 8;
        int cc = gc & 255;
        int r = half*Ff + k;
        float v = 0.f;
        if (cc < nc1)        v = W1[(size_t)r*ld1 + cc];
        else if (cc < ncols) v = W2[(size_t)r*ld2 + (cc - nc1)];
        Wsh[k*128 + c] = v;
    }
    __syncthreads();

    u64t acc[8][2];
    #pragma unroll
    for (int nl = 0; nl < 8; nl++){ acc[nl][0] = 0ull; acc[nl][1] = 0ull; }

    #pragma unroll 4
    for (int k = 0; k < Ff; k++){
        ulonglong2 w = *(const ulonglong2*)&Wsh[k*128 + tx*4];
        #pragma unroll
        for (int nl = 0; nl < 8; nl++){
            u64t a = snode2[(ty*8 + nl)*Ff + k];
            ffma2(acc[nl][0], a, w.x);
            ffma2(acc[nl][1], a, w.y);
        }
    }

    // bias (self half only)
    float bv[4];
    #pragma unroll
    for (int q = 0; q < 4; q++){
        int gc = cb + tx*4 + q;
        int half = gc >> 8;
        int cc = gc & 255;
        float b = 0.f;
        if (half == 0){
            if (cc < nc1)        b = b1[cc];
            else if (cc < ncols) b = b2[cc - nc1];
        }
        bv[q] = b;
    }

    #pragma unroll
    for (int nl = 0; nl < 8; nl++){
        int gn = n0 + ty*8 + nl;
        if (gn < Nn){
            float2 f0 = unpackf2(acc[nl][0]);
            float2 f1 = unpackf2(acc[nl][1]);
            __half2 h0 = __floats2half2_rn(f0.x + bv[0], f0.y + bv[1]);
            __half2 h1 = __floats2half2_rn(f1.x + bv[2], f1.y + bv[3]);
            uint2 o;
            o.x = *reinterpret_cast<unsigned*>(&h0);
            o.y = *reinterpret_cast<unsigned*>(&h1);
            *reinterpret_cast<uint2*>(g_P + (size_t)gn*PSTR + cb + tx*4) = o;
        }
    }
}

// ---------------- edge GEMM + fused BN column stats (fp32 Y out) ----------------
// Y[e][c] = P_self[i][c](+bias) + P_nbr[j][c] + edge_row @ Wedge[:,c]
// block (CG8, 8): tx = column group of 8, ty = edge group of 8 (64 edges/tile)
template<int CG8, int YSTR, int NCOLS>
__global__ __launch_bounds__(CG8*8)
void k_egemm(const float* __restrict__ ein, const int* __restrict__ eidx,
             const float* __restrict__ W1, int ld1,
             const float* __restrict__ W2, int ld2, int nc1)
{
    constexpr int COLS = CG8*8;
    extern __shared__ float smp[];
    float*  Wsh   = smp;                          // 41*COLS floats
    u64t*   ser2  = (u64t*)(Wsh + Ee*COLS);       // 64*41 dup pairs
    int*    sidx  = (int*)(ser2 + 64*Ee);         // 64
    double* sstat = (double*)(sidx + 64);         // 2*COLS

    const float* ei = ein ? ein : g_edge;
    int tx = threadIdx.x, ty = threadIdx.y;
    int tid = ty*CG8 + tx;
    const int nthr = CG8*8;

    for (int idx = tid; idx < Ee*COLS; idx += nthr){
        int k = idx / COLS, c = idx % COLS;
        float v = 0.f;
        if (c < nc1)        v = W1[(size_t)k*ld1 + c];
        else if (c < NCOLS) v = W2[(size_t)k*ld2 + (c - nc1)];
        Wsh[idx] = v;
    }
    for (int i = tid; i < 2*COLS; i += nthr) sstat[i] = 0.0;

    u64t s2[4] = {0,0,0,0}, q2[4] = {0,0,0,0};
    int ebase = ty*8;

    for (int t = blockIdx.x; t < NTILE64; t += gridDim.x){
        int e0 = t*64;
        __syncthreads();
        for (int idx = tid; idx < 64*Ee; idx += nthr)
            ser2[idx] = dupf2(ei[(size_t)e0*Ee + idx]);
        if (tid < 64) sidx[tid] = eidx[e0 + tid];
        __syncthreads();

        u64t acc[8][4];
        #pragma unroll
        for (int el = 0; el < 8; el++){
            int e = e0 + ebase + el;
            int i = e / Mm;
            int j = sidx[ebase + el];
            uint4 pv = *(const uint4*)(g_P + (size_t)i*PSTR + tx*8);
            uint4 nv = *(const uint4*)(g_P + (size_t)j*PSTR + PHALF + tx*8);
            const __half2* ph = (const __half2*)&pv;
            const __half2* nh = (const __half2*)&nv;
            #pragma unroll
            for (int p = 0; p < 4; p++){
                float2 a = __half22float2(ph[p]);
                float2 b = __half22float2(nh[p]);
                acc[el][p] = packf2(a.x + b.x, a.y + b.y);
            }
        }

        #pragma unroll 1
        for (int k = 0; k < Ee; k++){
            const ulonglong2* w2 = (const ulonglong2*)(Wsh + k*COLS + tx*8);
            ulonglong2 wA = w2[0], wB = w2[1];
            #pragma unroll
            for (int el = 0; el < 8; el++){
                u64t a = ser2[(ebase + el)*Ee + k];
                ffma2(acc[el][0], a, wA.x);
                ffma2(acc[el][1], a, wA.y);
                ffma2(acc[el][2], a, wB.x);
                ffma2(acc[el][3], a, wB.y);
            }
        }

        #pragma unroll
        for (int el = 0; el < 8; el++){
            #pragma unroll
            for (int p = 0; p < 4; p++){
                s2[p] = addf2(s2[p], acc[el][p]);
                ffma2(q2[p], acc[el][p], acc[el][p]);
            }
            float* yo = g_Y + (size_t)(e0 + ebase + el)*YSTR + tx*8;
            uint4 o1, o2;
            o1 = *reinterpret_cast<uint4*>(&acc[el][0]);   // cols 0..3 (two u64 pairs)
            o2 = *reinterpret_cast<uint4*>(&acc[el][2]);   // cols 4..7
            stcs16(yo,     o1);
            stcs16(yo + 4, o2);
        }
    }

    __syncthreads();
    #pragma unroll
    for (int p = 0; p < 4; p++){
        float2 sv = unpackf2(s2[p]);
        float2 qv = unpackf2(q2[p]);
        int c = tx*8 + 2*p;
        if (c < NCOLS){
            atomicAdd(&sstat[c], (double)sv.x);
            atomicAdd(&sstat[COLS + c], (double)qv.x);
        }
        if (c+1 < NCOLS){
            atomicAdd(&sstat[c+1], (double)sv.y);
            atomicAdd(&sstat[COLS + c + 1], (double)qv.y);
        }
    }
    __syncthreads();
    for (int c = tid; c < COLS; c += nthr){
        if (c < NCOLS){
            atomicAdd(&g_sumd[c], sstat[c]);
            atomicAdd(&g_sqd[c],  sstat[COLS + c]);
        }
    }
}

__global__ void k_finalize(int ncols, double inv_count)
{
    int c = threadIdx.x;
    if (c < ncols){
        double m = g_sumd[c]*inv_count;
        double var = g_sqd[c]*inv_count - m*m;
        g_mean[c] = (float)m;
        g_istd[c] = (float)(1.0/sqrt(var + 1e-5));
    }
}

// ---------------- gate + aggregate ----------------
__global__ void k_gate()
{
    __shared__ float ssum[112], ssq[112];
    for (int i = threadIdx.x; i < 112; i += 256){ ssum[i] = 0.f; ssq[i] = 0.f; }
    __syncthreads();

    int n    = blockIdx.x*8 + (threadIdx.x >> 5);
    int lane = threadIdx.x & 31;

    {
        int c0 = lane, c1 = lane + 32;
        float mf0 = g_mean[c0],    if0 = g_istd[c0];
        float mc0 = g_mean[64+c0], ic0 = g_istd[64+c0];
        float mf1 = g_mean[c1],    if1 = g_istd[c1];
        float mc1 = g_mean[64+c1], ic1 = g_istd[64+c1];
        float a0 = 0.f, a1 = 0.f;
        #pragma unroll
        for (int m = 0; m < Mm; m++){
            const float* y = g_Y + (size_t)(n*Mm + m)*YS_CONV;
            float vf = (y[c0]    - mf0)*if0;
            float vc = (y[64+c0] - mc0)*ic0;
            a0 += sigm_f(vf)*lrelu_f(vc);
            vf = (y[c1]    - mf1)*if1;
            vc = (y[64+c1] - mc1)*ic1;
            a1 += sigm_f(vf)*lrelu_f(vc);
        }
        g_aggr[(size_t)n*64 + c0] = a0;
        g_aggr[(size_t)n*64 + c1] = a1;
        atomicAdd(&ssum[c0], a0); atomicAdd(&ssq[c0], a0*a0);
        atomicAdd(&ssum[c1], a1); atomicAdd(&ssq[c1], a1*a1);
    }

    {
        int c0 = lane;
        int c1 = lane + 32;
        bool has1 = (c1 < Ee);
        float mf0 = g_mean[128+c0], if0 = g_istd[128+c0];
        float mc0 = g_mean[169+c0], ic0 = g_istd[169+c0];
        float mf1 = 0.f, if1 = 0.f, mc1 = 0.f, ic1 = 0.f;
        if (has1){
            mf1 = g_mean[128+c1]; if1 = g_istd[128+c1];
            mc1 = g_mean[169+c1]; ic1 = g_istd[169+c1];
        }
        float es0 = 0.f, eq0 = 0.f, es1 = 0.f, eq1 = 0.f;
        #pragma unroll
        for (int m = 0; m < Mm; m++){
            const float* y = g_Y + (size_t)(n*Mm + m)*YS_CONV;
            float vf = (y[128+c0] - mf0)*if0;
            float vc = (y[169+c0] - mc0)*ic0;
            float ge = sigm_f(vf)*lrelu_f(vc);
            g_G[(size_t)(n*Mm + m)*Ee + c0] = ge;
            es0 += ge; eq0 += ge*ge;
            if (has1){
                vf = (y[128+c1] - mf1)*if1;
                vc = (y[169+c1] - mc1)*ic1;
                float ge1 = sigm_f(vf)*lrelu_f(vc);
                g_G[(size_t)(n*Mm + m)*Ee + c1] = ge1;
                es1 += ge1; eq1 += ge1*ge1;
            }
        }
        atomicAdd(&ssum[64+c0], es0); atomicAdd(&ssq[64+c0], eq0);
        if (has1){ atomicAdd(&ssum[64+c1], es1); atomicAdd(&ssq[64+c1], eq1); }
    }

    __syncthreads();
    for (int i = threadIdx.x; i < 105; i += 256){
        atomicAdd(&g_sum2d[i], (double)ssum[i]);
        atomicAdd(&g_sq2d[i],  (double)ssq[i]);
    }
}

__global__ void k_finalize2()
{
    int c = threadIdx.x;
    if (c < 105){
        double cnt = (c < 64) ? (double)Nn : (double)NEe;
        double m = g_sum2d[c]/cnt;
        double var = g_sq2d[c]/cnt - m*m;
        g_mean2[c] = (float)m;
        g_istd2[c] = (float)(1.0/sqrt(var + 1e-5));
    }
}

// ---------------- residual updates (separate pass — proven correct) ----------------
__global__ void k_update(const float* __restrict__ edge_input)
{
    const int NA = Nn*Ff;
    int idx = blockIdx.x*256 + threadIdx.x;
    if (idx < NA){
        int c = idx & 63;
        float a = (g_aggr[idx] - g_mean2[c])*g_istd2[c];
        float v = g_node[idx] + a;
        g_node[idx] = lrelu_f(v);
    } else {
        size_t id2 = (size_t)idx - NA;
        if (id2 < (size_t)NEe*Ee){
            int c = (int)(id2 % Ee);
            float ge = (g_G[id2] - g_mean2[64+c])*g_istd2[64+c];
            const float* eiv = edge_input ? edge_input : g_edge;
            float v = eiv[id2] + ge;
            g_edge[id2] = lrelu_f(v);
        }
    }
}

// ---------------- output heads ----------------
__global__ void k_out(float* __restrict__ out)
{
    int e    = (blockIdx.x*256 + threadIdx.x) >> 5;
    int lane = threadIdx.x & 31;
    if (e >= NEe) return;
    const float* y = g_Y + (size_t)e*YS_FIN;
    float d = g_dist[e];
    float sd = 0.f, sc = 0.f;
    #pragma unroll
    for (int jj = 0; jj < 4; jj++){
        int c = lane + 32*jj;
        float v = (y[c] - g_mean[c])*g_istd[c] + d;
        sd += splus_f(v);
        int c2 = 128 + c;
        float v2 = (y[c2] - g_mean[c2])*g_istd[c2];
        sc += splus_f(v2);
    }
    #pragma unroll
    for (int o = 16; o > 0; o >>= 1){
        sd += __shfl_down_sync(0xffffffffu, sd, o);
        sc += __shfl_down_sync(0xffffffffu, sc, o);
    }
    if (lane == 0){
        out[(size_t)e*2 + 0] = sd*(1.f/128.f);
        out[(size_t)e*2 + 1] = sc*(1.f/(128.f*(float)Nn));
    }
}

// ---------------- host orchestration ----------------
extern "C" void kernel_launch(void* const* d_in, const int* in_sizes, int n_in,
                              void* d_out, int out_size)
{
    const float* node_fea = (const float*)d_in[0];
    const float* edge_fea = (const float*)d_in[1];
    const float* nbr_off  = (const float*)d_in[2];
    const float* atom_pos = (const float*)d_in[3];
    const float* cells    = (const float*)d_in[4];
    const int*   edge_idx = (const int*)d_in[5];
    const float* W_emb = (const float*)d_in[6];
    const float* b_emb = (const float*)d_in[7];
    const float* W_pn  = (const float*)d_in[8];
    const float* b_pn  = (const float*)d_in[9];
    const float* W_pe  = (const float*)d_in[10];
    const float* b_pe  = (const float*)d_in[11];
    const float* W_d   = (const float*)d_in[12];
    const float* b_d   = (const float*)d_in[13];
    const float* W_c   = (const float*)d_in[14];
    const float* b_c   = (const float*)d_in[15];
    float* out = (float*)d_out;

    (void)in_sizes; (void)n_in; (void)out_size;

    const int SM_PMAT = 64*Ff*8 + Ff*128*4;                        // 65536
    const int SM_CONV = Ee*224*4 + 64*Ee*8 + 64*4 + 2*224*8;       // 61568
    const int SM_FIN  = Ee*256*4 + 64*Ee*8 + 64*4 + 2*256*8;       // 67328
    cudaFuncSetAttribute((const void*)k_pmat,
                         cudaFuncAttributeMaxDynamicSharedMemorySize, SM_PMAT);
    cudaFuncSetAttribute((const void*)k_egemm<28,YS_CONV,210>,
                         cudaFuncAttributeMaxDynamicSharedMemorySize, SM_CONV);
    cudaFuncSetAttribute((const void*)k_egemm<32,YS_FIN,256>,
                         cudaFuncAttributeMaxDynamicSharedMemorySize, SM_FIN);

    k_emb<<<Nn/4, 256>>>(node_fea, W_emb, b_emb);
    k_dist<<<(NEe+255)/256, 256>>>(nbr_off, atom_pos, cells, edge_idx);

    const int NTOT = Nn*Ff + NEe*Ee;
    for (int l = 0; l < 3; l++){
        const float* Wn = W_pn + (size_t)l*Zz*NOUT;
        const float* We = W_pe + (size_t)l*Zz*EOUT;
        const float* bn = b_pn + l*NOUT;
        const float* be = b_pe + l*EOUT;
        const float* ein = (l == 0) ? edge_fea : nullptr;   // nullptr -> g_edge

        k_zero<<<1, 256>>>();
        k_pmat<<<dim3((Nn+63)/64, 4), dim3(32,8), SM_PMAT>>>(
            Wn, NOUT, NOUT, We, EOUT, 210, bn, be);
        k_egemm<28,YS_CONV,210><<<NBLK_EG, dim3(28,8), SM_CONV>>>(
            ein, edge_idx,
            Wn + 128*NOUT, NOUT,
            We + 128*EOUT, EOUT, NOUT);
        k_finalize<<<1, 256>>>(210, 1.0/(double)NEe);
        k_gate<<<Nn/8, 256>>>();
        k_finalize2<<<1, 128>>>();
        k_update<<<(NTOT+255)/256, 256>>>(ein);
    }

    // final heads
    k_zero<<<1, 256>>>();
    k_pmat<<<dim3((Nn+63)/64, 4), dim3(32,8), SM_PMAT>>>(
        W_d, Hh, Hh, W_c, Hh, 256, b_d, b_c);
    k_egemm<32,YS_FIN,256><<<NBLK_EG, dim3(32,8), SM_FIN>>>(
        nullptr, edge_idx,
        W_d + 128*Hh, Hh,
        W_c + 128*Hh, Hh, Hh);
    k_finalize<<<1, 256>>>(256, 1.0/(double)NEe);
    k_out<<<(NEe*32+255)/256, 256>>>(out);
}

// round 7
// speedup vs baseline: 1.3506x; 1.1010x over previous
#include <cuda_runtime.h>
#include <cuda_fp16.h>
#include <math.h>

#define Nn 50000
#define Mm 12
#define NEe (Nn*Mm)
#define OFd 92
#define Ff 64
#define Ee 41
#define Zz 169
#define Hh 128
#define NOUT 128
#define EOUT 82
#define PSTR 512          // P row stride in halves: [0,256) self(+bias), [256,512) nbr
#define PHALF 256
#define YS_CONV 224       // conv Y stride in floats (210 real)
#define YS_FIN 256
#define NTILE64 (NEe/64)  // 9375
#define NBLK_EG 444

// ---------------- scratch ----------------
__device__ __align__(16) float  g_node[Nn*Ff];
__device__ __align__(16) float  g_edge[(size_t)NEe*Ee];
__device__ __align__(16) __half g_P[(size_t)Nn*PSTR];        // 51.2 MB (L2-resident)
__device__ __align__(16) float  g_Y[(size_t)NEe*256];        // 614 MB
__device__ __align__(16) float  g_G[(size_t)NEe*Ee];
__device__ __align__(16) float  g_aggr[Nn*Ff];
__device__ __align__(16) float  g_dist[NEe];
__device__ double g_sumd[256], g_sqd[256];
__device__ float  g_mean[256], g_istd[256];
__device__ double g_sum2d[112], g_sq2d[112];
__device__ float  g_mean2[112], g_istd2[112];

typedef unsigned long long u64t;

__device__ __forceinline__ float lrelu_f(float v){ return v > 0.f ? v : 0.01f*v; }
__device__ __forceinline__ float sigm_f(float x){ return 1.f/(1.f+expf(-x)); }
__device__ __forceinline__ float splus_f(float x){ return fmaxf(x,0.f) + log1pf(expf(-fabsf(x))); }

// ---- packed f32x2 helpers (sm_103a) ----
__device__ __forceinline__ u64t dupf2(float v){
    u64t p; asm("mov.b64 %0, {%1, %1};" : "=l"(p) : "f"(v)); return p;
}
__device__ __forceinline__ u64t packf2(float x, float y){
    u64t p; asm("mov.b64 %0, {%1, %2};" : "=l"(p) : "f"(x), "f"(y)); return p;
}
__device__ __forceinline__ void ffma2(u64t &d, u64t a, u64t b){
    asm("fma.rn.f32x2 %0, %1, %2, %3;" : "=l"(d) : "l"(a), "l"(b), "l"(d));
}
__device__ __forceinline__ u64t addf2(u64t a, u64t b){
    u64t d; asm("add.rn.f32x2 %0, %1, %2;" : "=l"(d) : "l"(a), "l"(b)); return d;
}
__device__ __forceinline__ float2 unpackf2(u64t p){
    float2 r; asm("mov.b64 {%0, %1}, %2;" : "=f"(r.x), "=f"(r.y) : "l"(p)); return r;
}
// streaming (evict-first) 16B store
__device__ __forceinline__ void stcs16(void* p, uint4 v){
    asm volatile("st.global.cs.v4.b32 [%0], {%1,%2,%3,%4};"
                 :: "l"(p), "r"(v.x), "r"(v.y), "r"(v.z), "r"(v.w) : "memory");
}

// ---------------- node embedding ----------------
__global__ void k_emb(const float* __restrict__ nf, const float* __restrict__ W,
                      const float* __restrict__ b)
{
    __shared__ float srow[4][OFd];
    int n0 = blockIdx.x*4;
    for (int idx = threadIdx.x; idx < 4*OFd; idx += 256){
        int nl = idx/OFd, k = idx%OFd;
        srow[nl][k] = nf[(size_t)(n0+nl)*OFd + k];
    }
    __syncthreads();
    int c  = threadIdx.x & 63;
    int nl = threadIdx.x >> 6;
    float acc = b[c];
    #pragma unroll
    for (int k = 0; k < OFd; k++) acc += srow[nl][k]*W[k*Ff + c];
    g_node[(size_t)(n0+nl)*Ff + c] = acc;
}

// ---------------- distances ----------------
__global__ void k_dist(const float* __restrict__ off, const float* __restrict__ pos,
                       const float* __restrict__ cells, const int* __restrict__ eidx)
{
    int e = blockIdx.x*256 + threadIdx.x;
    if (e >= NEe) return;
    int n = e / Mm;
    int j = eidx[e];
    float o0 = off[(size_t)e*3+0], o1 = off[(size_t)e*3+1], o2 = off[(size_t)e*3+2];
    const float* C = cells + (size_t)n*9;
    float d0 = pos[(size_t)j*3+0] + o0*C[0] + o1*C[3] + o2*C[6] - pos[(size_t)n*3+0];
    float d1 = pos[(size_t)j*3+1] + o0*C[1] + o1*C[4] + o2*C[7] - pos[(size_t)n*3+1];
    float d2 = pos[(size_t)j*3+2] + o0*C[2] + o1*C[5] + o2*C[8] - pos[(size_t)n*3+2];
    g_dist[e] = sqrtf(d0*d0 + d1*d1 + d2*d2 + 1e-12f);
}

__global__ void k_zero()
{
    int t = threadIdx.x;
    if (t < 256){ g_sumd[t] = 0.0; g_sqd[t] = 0.0; }
    if (t < 112){ g_sum2d[t] = 0.0; g_sq2d[t] = 0.0; }
}

// ---------------- P = node @ W  (fp16 out; bias folded into self half) ----------------
// block (32,8): tx = col quad (128 cols/block), ty covers 8 nodes (64 nodes/block)
// grid ((Nn+63)/64, 4); smem 48KB -> 4 blocks/SM
__global__ __launch_bounds__(256)
void k_pmat(const float* __restrict__ W1, int ld1, int nc1,
            const float* __restrict__ W2, int ld2, int ncols,
            const float* __restrict__ b1, const float* __restrict__ b2)
{
    extern __shared__ char smraw[];
    float* snode = (float*)smraw;                 // 64 nodes x 64 k (16 KB)
    float* Wsh   = snode + 64*Ff;                 // [64][128] (32 KB)
    int tx = threadIdx.x, ty = threadIdx.y;
    int tid = ty*32 + tx;
    int n0 = blockIdx.x*64;
    int cb = blockIdx.y*128;

    for (int idx = tid; idx < 64*Ff; idx += 256){
        int gn = n0 + (idx >> 6);
        snode[idx] = (gn < Nn) ? g_node[(size_t)n0*Ff + idx] : 0.f;
    }
    for (int idx = tid; idx < Ff*128; idx += 256){
        int k = idx >> 7, c = idx & 127;
        int gc = cb + c;
        int half = gc >> 8;
        int cc = gc & 255;
        int r = half*Ff + k;
        float v = 0.f;
        if (cc < nc1)        v = W1[(size_t)r*ld1 + cc];
        else if (cc < ncols) v = W2[(size_t)r*ld2 + (cc - nc1)];
        Wsh[k*128 + c] = v;
    }
    __syncthreads();

    u64t acc[8][2];
    #pragma unroll
    for (int nl = 0; nl < 8; nl++){ acc[nl][0] = 0ull; acc[nl][1] = 0ull; }

    #pragma unroll 4
    for (int k = 0; k < Ff; k++){
        ulonglong2 w = *(const ulonglong2*)&Wsh[k*128 + tx*4];
        #pragma unroll
        for (int nl = 0; nl < 8; nl++){
            u64t a = dupf2(snode[(ty*8 + nl)*Ff + k]);
            ffma2(acc[nl][0], a, w.x);
            ffma2(acc[nl][1], a, w.y);
        }
    }

    // bias (self half only)
    float bv[4];
    #pragma unroll
    for (int q = 0; q < 4; q++){
        int gc = cb + tx*4 + q;
        int half = gc >> 8;
        int cc = gc & 255;
        float b = 0.f;
        if (half == 0){
            if (cc < nc1)        b = b1[cc];
            else if (cc < ncols) b = b2[cc - nc1];
        }
        bv[q] = b;
    }

    #pragma unroll
    for (int nl = 0; nl < 8; nl++){
        int gn = n0 + ty*8 + nl;
        if (gn < Nn){
            float2 f0 = unpackf2(acc[nl][0]);
            float2 f1 = unpackf2(acc[nl][1]);
            __half2 h0 = __floats2half2_rn(f0.x + bv[0], f0.y + bv[1]);
            __half2 h1 = __floats2half2_rn(f1.x + bv[2], f1.y + bv[3]);
            uint2 o;
            o.x = *reinterpret_cast<unsigned*>(&h0);
            o.y = *reinterpret_cast<unsigned*>(&h1);
            *reinterpret_cast<uint2*>(g_P + (size_t)gn*PSTR + cb + tx*4) = o;
        }
    }
}

// ---------------- edge GEMM + fused BN column stats (fp32 Y out) ----------------
// Y[e][c] = P_self[i][c](+bias) + P_nbr[j][c] + edge_row @ Wedge[:,c]
// block (CG8, 8): tx = column group of 8, ty = edge group of 8 (64 edges/tile)
template<int CG8, int YSTR, int NCOLS>
__global__ __launch_bounds__(CG8*8)
void k_egemm(const float* __restrict__ ein, const int* __restrict__ eidx,
             const float* __restrict__ W1, int ld1,
             const float* __restrict__ W2, int ld2, int nc1)
{
    constexpr int COLS = CG8*8;
    extern __shared__ float smp[];
    float*  Wsh   = smp;                          // 41*COLS floats
    u64t*   ser2  = (u64t*)(Wsh + Ee*COLS);       // 64*41 dup pairs
    int*    sidx  = (int*)(ser2 + 64*Ee);         // 64
    double* sstat = (double*)(sidx + 64);         // 2*COLS

    const float* ei = ein ? ein : g_edge;
    int tx = threadIdx.x, ty = threadIdx.y;
    int tid = ty*CG8 + tx;
    const int nthr = CG8*8;

    for (int idx = tid; idx < Ee*COLS; idx += nthr){
        int k = idx / COLS, c = idx % COLS;
        float v = 0.f;
        if (c < nc1)        v = W1[(size_t)k*ld1 + c];
        else if (c < NCOLS) v = W2[(size_t)k*ld2 + (c - nc1)];
        Wsh[idx] = v;
    }
    for (int i = tid; i < 2*COLS; i += nthr) sstat[i] = 0.0;

    u64t s2[4] = {0,0,0,0}, q2[4] = {0,0,0,0};
    int ebase = ty*8;

    for (int t = blockIdx.x; t < NTILE64; t += gridDim.x){
        int e0 = t*64;
        __syncthreads();
        for (int idx = tid; idx < 64*Ee; idx += nthr)
            ser2[idx] = dupf2(ei[(size_t)e0*Ee + idx]);
        if (tid < 64) sidx[tid] = eidx[e0 + tid];
        __syncthreads();

        u64t acc[8][4];
        #pragma unroll
        for (int el = 0; el < 8; el++){
            int e = e0 + ebase + el;
            int i = e / Mm;
            int j = sidx[ebase + el];
            uint4 pv = *(const uint4*)(g_P + (size_t)i*PSTR + tx*8);
            uint4 nv = *(const uint4*)(g_P + (size_t)j*PSTR + PHALF + tx*8);
            const __half2* ph = (const __half2*)&pv;
            const __half2* nh = (const __half2*)&nv;
            #pragma unroll
            for (int p = 0; p < 4; p++){
                float2 a = __half22float2(ph[p]);
                float2 b = __half22float2(nh[p]);
                acc[el][p] = packf2(a.x + b.x, a.y + b.y);
            }
        }

        #pragma unroll 2
        for (int k = 0; k < Ee; k++){
            const ulonglong2* w2 = (const ulonglong2*)(Wsh + k*COLS + tx*8);
            ulonglong2 wA = w2[0], wB = w2[1];
            #pragma unroll
            for (int el = 0; el < 8; el++){
                u64t a = ser2[(ebase + el)*Ee + k];
                ffma2(acc[el][0], a, wA.x);
                ffma2(acc[el][1], a, wA.y);
                ffma2(acc[el][2], a, wB.x);
                ffma2(acc[el][3], a, wB.y);
            }
        }

        #pragma unroll
        for (int el = 0; el < 8; el++){
            #pragma unroll
            for (int p = 0; p < 4; p++){
                s2[p] = addf2(s2[p], acc[el][p]);
                ffma2(q2[p], acc[el][p], acc[el][p]);
            }
            float* yo = g_Y + (size_t)(e0 + ebase + el)*YSTR + tx*8;
            uint4 o1, o2;
            o1 = *reinterpret_cast<uint4*>(&acc[el][0]);   // cols 0..3
            o2 = *reinterpret_cast<uint4*>(&acc[el][2]);   // cols 4..7
            stcs16(yo,     o1);
            stcs16(yo + 4, o2);
        }
    }

    __syncthreads();
    #pragma unroll
    for (int p = 0; p < 4; p++){
        float2 sv = unpackf2(s2[p]);
        float2 qv = unpackf2(q2[p]);
        int c = tx*8 + 2*p;
        if (c < NCOLS){
            atomicAdd(&sstat[c], (double)sv.x);
            atomicAdd(&sstat[COLS + c], (double)qv.x);
        }
        if (c+1 < NCOLS){
            atomicAdd(&sstat[c+1], (double)sv.y);
            atomicAdd(&sstat[COLS + c + 1], (double)qv.y);
        }
    }
    __syncthreads();
    for (int c = tid; c < COLS; c += nthr){
        if (c < NCOLS){
            atomicAdd(&g_sumd[c], sstat[c]);
            atomicAdd(&g_sqd[c],  sstat[COLS + c]);
        }
    }
}

__global__ void k_finalize(int ncols, double inv_count)
{
    int c = threadIdx.x;
    if (c < ncols){
        double m = g_sumd[c]*inv_count;
        double var = g_sqd[c]*inv_count - m*m;
        g_mean[c] = (float)m;
        g_istd[c] = (float)(1.0/sqrt(var + 1e-5));
    }
}

// ---------------- gate + aggregate ----------------
__global__ void k_gate()
{
    __shared__ float ssum[112], ssq[112];
    for (int i = threadIdx.x; i < 112; i += 256){ ssum[i] = 0.f; ssq[i] = 0.f; }
    __syncthreads();

    int n    = blockIdx.x*8 + (threadIdx.x >> 5);
    int lane = threadIdx.x & 31;

    {
        int c0 = lane, c1 = lane + 32;
        float mf0 = g_mean[c0],    if0 = g_istd[c0];
        float mc0 = g_mean[64+c0], ic0 = g_istd[64+c0];
        float mf1 = g_mean[c1],    if1 = g_istd[c1];
        float mc1 = g_mean[64+c1], ic1 = g_istd[64+c1];
        float a0 = 0.f, a1 = 0.f;
        #pragma unroll
        for (int m = 0; m < Mm; m++){
            const float* y = g_Y + (size_t)(n*Mm + m)*YS_CONV;
            float vf = (__ldcs(y+c0)    - mf0)*if0;
            float vc = (__ldcs(y+64+c0) - mc0)*ic0;
            a0 += sigm_f(vf)*lrelu_f(vc);
            vf = (__ldcs(y+c1)    - mf1)*if1;
            vc = (__ldcs(y+64+c1) - mc1)*ic1;
            a1 += sigm_f(vf)*lrelu_f(vc);
        }
        g_aggr[(size_t)n*64 + c0] = a0;
        g_aggr[(size_t)n*64 + c1] = a1;
        atomicAdd(&ssum[c0], a0); atomicAdd(&ssq[c0], a0*a0);
        atomicAdd(&ssum[c1], a1); atomicAdd(&ssq[c1], a1*a1);
    }

    {
        int c0 = lane;
        int c1 = lane + 32;
        bool has1 = (c1 < Ee);
        float mf0 = g_mean[128+c0], if0 = g_istd[128+c0];
        float mc0 = g_mean[169+c0], ic0 = g_istd[169+c0];
        float mf1 = 0.f, if1 = 0.f, mc1 = 0.f, ic1 = 0.f;
        if (has1){
            mf1 = g_mean[128+c1]; if1 = g_istd[128+c1];
            mc1 = g_mean[169+c1]; ic1 = g_istd[169+c1];
        }
        float es0 = 0.f, eq0 = 0.f, es1 = 0.f, eq1 = 0.f;
        #pragma unroll
        for (int m = 0; m < Mm; m++){
            const float* y = g_Y + (size_t)(n*Mm + m)*YS_CONV;
            float vf = (__ldcs(y+128+c0) - mf0)*if0;
            float vc = (__ldcs(y+169+c0) - mc0)*ic0;
            float ge = sigm_f(vf)*lrelu_f(vc);
            g_G[(size_t)(n*Mm + m)*Ee + c0] = ge;
            es0 += ge; eq0 += ge*ge;
            if (has1){
                vf = (__ldcs(y+128+c1) - mf1)*if1;
                vc = (__ldcs(y+169+c1) - mc1)*ic1;
                float ge1 = sigm_f(vf)*lrelu_f(vc);
                g_G[(size_t)(n*Mm + m)*Ee + c1] = ge1;
                es1 += ge1; eq1 += ge1*ge1;
            }
        }
        atomicAdd(&ssum[64+c0], es0); atomicAdd(&ssq[64+c0], eq0);
        if (has1){ atomicAdd(&ssum[64+c1], es1); atomicAdd(&ssq[64+c1], eq1); }
    }

    __syncthreads();
    for (int i = threadIdx.x; i < 105; i += 256){
        atomicAdd(&g_sum2d[i], (double)ssum[i]);
        atomicAdd(&g_sq2d[i],  (double)ssq[i]);
    }
}

__global__ void k_finalize2()
{
    int c = threadIdx.x;
    if (c < 105){
        double cnt = (c < 64) ? (double)Nn : (double)NEe;
        double m = g_sum2d[c]/cnt;
        double var = g_sq2d[c]/cnt - m*m;
        g_mean2[c] = (float)m;
        g_istd2[c] = (float)(1.0/sqrt(var + 1e-5));
    }
}

// ---------------- residual updates (separate pass — proven correct) ----------------
__global__ void k_update(const float* __restrict__ edge_input)
{
    const int NA = Nn*Ff;
    int idx = blockIdx.x*256 + threadIdx.x;
    if (idx < NA){
        int c = idx & 63;
        float a = (g_aggr[idx] - g_mean2[c])*g_istd2[c];
        float v = g_node[idx] + a;
        g_node[idx] = lrelu_f(v);
    } else {
        size_t id2 = (size_t)idx - NA;
        if (id2 < (size_t)NEe*Ee){
            int c = (int)(id2 % Ee);
            float ge = (g_G[id2] - g_mean2[64+c])*g_istd2[64+c];
            const float* eiv = edge_input ? edge_input : g_edge;
            float v = eiv[id2] + ge;
            g_edge[id2] = lrelu_f(v);
        }
    }
}

// ---------------- output heads ----------------
__global__ void k_out(float* __restrict__ out)
{
    int e    = (blockIdx.x*256 + threadIdx.x) >> 5;
    int lane = threadIdx.x & 31;
    if (e >= NEe) return;
    const float* y = g_Y + (size_t)e*YS_FIN;
    float d = g_dist[e];
    float sd = 0.f, sc = 0.f;
    #pragma unroll
    for (int jj = 0; jj < 4; jj++){
        int c = lane + 32*jj;
        float v = (__ldcs(y+c) - g_mean[c])*g_istd[c] + d;
        sd += splus_f(v);
        int c2 = 128 + c;
        float v2 = (__ldcs(y+c2) - g_mean[c2])*g_istd[c2];
        sc += splus_f(v2);
    }
    #pragma unroll
    for (int o = 16; o > 0; o >>= 1){
        sd += __shfl_down_sync(0xffffffffu, sd, o);
        sc += __shfl_down_sync(0xffffffffu, sc, o);
    }
    if (lane == 0){
        out[(size_t)e*2 + 0] = sd*(1.f/128.f);
        out[(size_t)e*2 + 1] = sc*(1.f/(128.f*(float)Nn));
    }
}

// ---------------- host orchestration ----------------
extern "C" void kernel_launch(void* const* d_in, const int* in_sizes, int n_in,
                              void* d_out, int out_size)
{
    const float* node_fea = (const float*)d_in[0];
    const float* edge_fea = (const float*)d_in[1];
    const float* nbr_off  = (const float*)d_in[2];
    const float* atom_pos = (const float*)d_in[3];
    const float* cells    = (const float*)d_in[4];
    const int*   edge_idx = (const int*)d_in[5];
    const float* W_emb = (const float*)d_in[6];
    const float* b_emb = (const float*)d_in[7];
    const float* W_pn  = (const float*)d_in[8];
    const float* b_pn  = (const float*)d_in[9];
    const float* W_pe  = (const float*)d_in[10];
    const float* b_pe  = (const float*)d_in[11];
    const float* W_d   = (const float*)d_in[12];
    const float* b_d   = (const float*)d_in[13];
    const float* W_c   = (const float*)d_in[14];
    const float* b_c   = (const float*)d_in[15];
    float* out = (float*)d_out;

    (void)in_sizes; (void)n_in; (void)out_size;

    const int SM_PMAT = 64*Ff*4 + Ff*128*4;                        // 49152
    const int SM_CONV = Ee*224*4 + 64*Ee*8 + 64*4 + 2*224*8;       // 61568
    const int SM_FIN  = Ee*256*4 + 64*Ee*8 + 64*4 + 2*256*8;       // 67328
    cudaFuncSetAttribute((const void*)k_pmat,
                         cudaFuncAttributeMaxDynamicSharedMemorySize, SM_PMAT);
    cudaFuncSetAttribute((const void*)k_egemm<28,YS_CONV,210>,
                         cudaFuncAttributeMaxDynamicSharedMemorySize, SM_CONV);
    cudaFuncSetAttribute((const void*)k_egemm<32,YS_FIN,256>,
                         cudaFuncAttributeMaxDynamicSharedMemorySize, SM_FIN);

    k_emb<<<Nn/4, 256>>>(node_fea, W_emb, b_emb);

    const int NTOT = Nn*Ff + NEe*Ee;
    for (int l = 0; l < 3; l++){
        const float* Wn = W_pn + (size_t)l*Zz*NOUT;
        const float* We = W_pe + (size_t)l*Zz*EOUT;
        const float* bn = b_pn + l*NOUT;
        const float* be = b_pe + l*EOUT;
        const float* ein = (l == 0) ? edge_fea : nullptr;   // nullptr -> g_edge

        k_pmat<<<dim3((Nn+63)/64, 4), dim3(32,8), SM_PMAT>>>(
            Wn, NOUT, NOUT, We, EOUT, 210, bn, be);
        k_zero<<<1, 256>>>();
        k_egemm<28,YS_CONV,210><<<NBLK_EG, dim3(28,8), SM_CONV>>>(
            ein, edge_idx,
            Wn + 128*NOUT, NOUT,
            We + 128*EOUT, EOUT, NOUT);
        k_finalize<<<1, 256>>>(210, 1.0/(double)NEe);
        k_gate<<<Nn/8, 256>>>();
        k_finalize2<<<1, 128>>>();
        k_update<<<(NTOT+255)/256, 256>>>(ein);
    }

    // final heads
    k_pmat<<<dim3((Nn+63)/64, 4), dim3(32,8), SM_PMAT>>>(
        W_d, Hh, Hh, W_c, Hh, 256, b_d, b_c);
    k_zero<<<1, 256>>>();
    k_egemm<32,YS_FIN,256><<<NBLK_EG, dim3(32,8), SM_FIN>>>(
        nullptr, edge_idx,
        W_d + 128*Hh, Hh,
        W_c + 128*Hh, Hh, Hh);
    k_finalize<<<1, 256>>>(256, 1.0/(double)NEe);
    k_dist<<<(NEe+255)/256, 256>>>(nbr_off, atom_pos, cells, edge_idx);
    k_out<<<(NEe*32+255)/256, 256>>>(out);
}